// round 16
// baseline (speedup 1.0000x reference)
#include <cuda_runtime.h>
#include <cstdint>

// ---------------------------------------------------------------------------
// Shapes
// ---------------------------------------------------------------------------
#define BT   12
#define CF   1024
#define CQ   128
#define NTOK 2401
#define NP   2432
#define HF   49

// ---------------------------------------------------------------------------
// Scratch
// ---------------------------------------------------------------------------
__device__ float g_XT [(size_t)BT * NP * CF];   // raw XT (q/k path)
__device__ float g_XTh[(size_t)BT * NP * CF];   // tf32-rounded XT (v path)
__device__ float g_Wvh[(size_t)CF * CF];        // tf32-rounded Wv
__device__ float g_QT [(size_t)BT * NP * CQ];   // raw q
__device__ float g_KT [(size_t)BT * NP * CQ];   // raw k
__device__ float g_V  [(size_t)BT * CF * NP];   // tf32-rounded v (incl bias)
__device__ float g_ATT[(size_t)BT * NP * NP];   // raw scores -> tf32-rounded probs

__device__ __forceinline__ uint32_t f2tf(float f) {
    uint32_t u; asm("cvt.rna.tf32.f32 %0, %1;" : "=r"(u) : "f"(f)); return u;
}
__device__ __forceinline__ float tf32f(float f) { return __uint_as_float(f2tf(f)); }
__device__ __forceinline__ uint32_t u2tf(uint32_t x) {
    uint32_t u; asm("cvt.rna.tf32.f32 %0, %1;" : "=r"(u) : "f"(__uint_as_float(x))); return u;
}
__device__ __forceinline__ uint32_t smem_u32(const void* p) {
    uint32_t a;
    asm("{ .reg .u64 t; cvta.to.shared.u64 t, %1; cvt.u32.u64 %0, t; }" : "=r"(a) : "l"(p));
    return a;
}

// residual gather: x[bt][c][n] straight from inputs (L2-resident)
__device__ __forceinline__ float gather_x(const float* __restrict__ img,
                                          const float* __restrict__ tac,
                                          int bt, int c, int n) {
    int i = n / HF, j = n % HF;
    return (c < 512)
        ? tac[(((size_t)bt * 512 + c) * 7 + (i / 7)) * 7 + (j / 7)]
        : img[(((size_t)bt * 512 + (c - 512)) * 7 + (i % 7)) * 7 + (j % 7)];
}

__device__ __forceinline__ void mma_tf32(float c[4], const uint32_t a[4], const uint32_t b[2]) {
    asm volatile(
        "mma.sync.aligned.m16n8k8.row.col.f32.tf32.tf32.f32 "
        "{%0,%1,%2,%3}, {%4,%5,%6,%7}, {%8,%9}, {%0,%1,%2,%3};"
        : "+f"(c[0]), "+f"(c[1]), "+f"(c[2]), "+f"(c[3])
        : "r"(a[0]), "r"(a[1]), "r"(a[2]), "r"(a[3]), "r"(b[0]), "r"(b[1]));
}

#define CP_ASYNC16(dst_u32, src_ptr) \
    asm volatile("cp.async.cg.shared.global [%0], [%1], 16;" :: "r"(dst_u32), "l"(src_ptr) : "memory")
#define CP_COMMIT() asm volatile("cp.async.commit_group;" ::: "memory")
#define CP_WAIT0()  asm volatile("cp.async.wait_group 0;" ::: "memory")
#define CP_WAIT1()  asm volatile("cp.async.wait_group 1;" ::: "memory")

// ---------------------------------------------------------------------------
// 1) XT raw + rounded (zero rows for n >= NTOK)
// ---------------------------------------------------------------------------
__global__ void build_xt_kernel(const float* __restrict__ img,
                                const float* __restrict__ tac) {
    int c = blockIdx.x * 256 + threadIdx.x;
    int n = blockIdx.y, bt = blockIdx.z;
    if (c >= CF) return;
    float v = 0.0f;
    if (n < NTOK) v = gather_x(img, tac, bt, c, n);
    size_t base = ((size_t)bt * NP + n) * CF + c;
    g_XT[base]  = v;
    g_XTh[base] = tf32f(v);
}

// ---------------------------------------------------------------------------
// 1b) Wv -> rounded
// ---------------------------------------------------------------------------
__global__ void prep_round_kernel(const float* __restrict__ src,
                                  float* __restrict__ dst, int n) {
    int i = blockIdx.x * 256 + threadIdx.x;
    if (i < n) dst[i] = tf32f(src[i]);
}

// ---------------------------------------------------------------------------
// 2) row softmax (m < 2401), writes tf32-rounded probs, zeroes padding
// ---------------------------------------------------------------------------
__global__ __launch_bounds__(256)
void softmax_kernel() {
    __shared__ float row[NTOK];
    __shared__ float red[256];
    const int n = blockIdx.x, bt = blockIdx.y;
    float* base = g_ATT + ((size_t)bt * NP + n) * NP;
    const int t = threadIdx.x;

    float mx = -1e30f;
    for (int m = t; m < NTOK; m += 256) { float v = base[m]; row[m] = v; mx = fmaxf(mx, v); }
    red[t] = mx; __syncthreads();
    for (int s = 128; s > 0; s >>= 1) { if (t < s) red[t] = fmaxf(red[t], red[t + s]); __syncthreads(); }
    mx = red[0]; __syncthreads();

    float sum = 0.0f;
    for (int m = t; m < NTOK; m += 256) { float e = __expf(row[m] - mx); row[m] = e; sum += e; }
    red[t] = sum; __syncthreads();
    for (int s = 128; s > 0; s >>= 1) { if (t < s) red[t] += red[t + s]; __syncthreads(); }
    float inv = 1.0f / red[0];

    for (int m = t; m < NTOK; m += 256) base[m] = tf32f(row[m] * inv);
    for (int m = NTOK + t; m < NP; m += 256) base[m] = 0.0f;
}

// ---------------------------------------------------------------------------
// Shared tiling constants (stride-36 layout, conflict-free scalar LDS)
// ---------------------------------------------------------------------------
#define LDS_S 36
#define TILEW (128 * LDS_S)            // words per 128x32 tile
#define STAGEW (2 * TILEW)             // A+B per stage
#define SMEM_T3 (3 * STAGEW * 4)       // 110592 B: 3-stage pipeline, 2 CTAs/SM

// ---------------------------------------------------------------------------
// 3) SPLIT=1 GEMM on PRE-ROUNDED operands, 3-stage cp.async pipeline
//    (prefetch distance 2), one barrier per chunk, 2 CTAs/SM.
//    C[M,N] = A[M,K] @ B[N,K]^T (both K-major). 256 thr, warp tile 64x32.
//    EPI 0: C = tf32f(acc + bias[row])                (v writeback)
//    EPI 1: C = gamma*acc + gather_x(row,col), col<NTOK  (final output)
// ---------------------------------------------------------------------------
template <int EPI>
__global__ __launch_bounds__(256, 2)
void gemm_async_kernel(const float* __restrict__ A, int lda, size_t strideA,
                       const float* __restrict__ B, int ldb, size_t strideB,
                       int K,
                       const float* __restrict__ bias,
                       const float* __restrict__ gamma,
                       const float* __restrict__ img,
                       const float* __restrict__ tac,
                       float* __restrict__ C, int ldc, size_t strideC) {
    extern __shared__ uint32_t sm[];
    const uint32_t smem_base = smem_u32(sm);

    const int bt = blockIdx.z;
    const int m0 = blockIdx.x * 128;
    const int n0 = blockIdx.y * 128;
    const float* Ab = A + (size_t)bt * strideA + (size_t)m0 * lda;
    const float* Bb = B + (size_t)bt * strideB + (size_t)n0 * ldb;

    const int t = threadIdx.x;
    const int wid = t >> 5, lane = t & 31;
    const int warp_m = wid & 1, warp_n = wid >> 1;
    const int l4 = lane >> 2, lm = lane & 3;

    const int prow = t >> 1;
    const int pcol = (t & 1) * 16;
    const float* aRow = Ab + (size_t)prow * lda + pcol;
    const float* bRow = Bb + (size_t)prow * ldb + pcol;
    const uint32_t sA0 = smem_base + (prow * LDS_S + pcol) * 4;
    const uint32_t sB0 = sA0 + TILEW * 4;

    float acc[4][4][4];
    #pragma unroll
    for (int mi = 0; mi < 4; mi++)
        #pragma unroll
        for (int ni = 0; ni < 4; ni++)
            #pragma unroll
            for (int r = 0; r < 4; r++) acc[mi][ni][r] = 0.0f;

    const int NCH = K / 32;

    #define ISSUE1(stg, koff) do {                                             \
        const uint32_t _dA = sA0 + (uint32_t)(stg) * (STAGEW * 4);             \
        const uint32_t _dB = sB0 + (uint32_t)(stg) * (STAGEW * 4);             \
        _Pragma("unroll")                                                      \
        for (int q = 0; q < 4; q++) {                                          \
            CP_ASYNC16(_dA + q * 16, aRow + (koff) + q * 4);                   \
            CP_ASYNC16(_dB + q * 16, bRow + (koff) + q * 4);                   \
        }                                                                      \
        CP_COMMIT();                                                           \
    } while (0)

    ISSUE1(0, 0);
    if (NCH > 1) ISSUE1(1, 32);

    for (int ch = 0; ch < NCH; ch++) {
        if (ch + 1 < NCH) CP_WAIT1(); else CP_WAIT0();
        __syncthreads();
        if (ch + 2 < NCH) ISSUE1((ch + 2) % 3, (ch + 2) * 32);

        const uint32_t* as = sm + (ch % 3) * STAGEW;
        const uint32_t* bs = as + TILEW;
        #pragma unroll
        for (int g = 0; g < 4; g++) {
            const int kk = g * 8;
            uint32_t b[4][2];
            #pragma unroll
            for (int ni = 0; ni < 4; ni++) {
                const int base = (warp_n * 32 + ni * 8 + l4) * LDS_S + kk + lm;
                b[ni][0] = bs[base];
                b[ni][1] = bs[base + 4];
            }
            #pragma unroll
            for (int mi = 0; mi < 4; mi++) {
                const int base = (warp_m * 64 + mi * 16 + l4) * LDS_S + kk + lm;
                uint32_t a[4];
                a[0] = as[base];
                a[1] = as[base + 8 * LDS_S];
                a[2] = as[base + 4];
                a[3] = as[base + 8 * LDS_S + 4];
                #pragma unroll
                for (int ni = 0; ni < 4; ni++) mma_tf32(acc[mi][ni], a, b[ni]);
            }
        }
    }
    #undef ISSUE1

    float* Cb = C + (size_t)bt * strideC;
    if (EPI == 0) {
        #pragma unroll
        for (int mi = 0; mi < 4; mi++) {
            const int gr = m0 + warp_m * 64 + mi * 16 + l4;
            const float bv0 = bias[gr], bv8 = bias[gr + 8];
            #pragma unroll
            for (int ni = 0; ni < 4; ni++) {
                const int gc = n0 + warp_n * 32 + ni * 8 + lm * 2;
                float2 o0 = { tf32f(acc[mi][ni][0] + bv0), tf32f(acc[mi][ni][1] + bv0) };
                float2 o1 = { tf32f(acc[mi][ni][2] + bv8), tf32f(acc[mi][ni][3] + bv8) };
                *reinterpret_cast<float2*>(&Cb[(size_t)gr * ldc + gc]) = o0;
                *reinterpret_cast<float2*>(&Cb[(size_t)(gr + 8) * ldc + gc]) = o1;
            }
        }
    } else {
        const float g = __ldg(gamma);
        #pragma unroll
        for (int mi = 0; mi < 4; mi++) {
            const int gr = m0 + warp_m * 64 + mi * 16 + l4;
            #pragma unroll
            for (int ni = 0; ni < 4; ni++) {
                const int gc = n0 + warp_n * 32 + ni * 8 + lm * 2;
                if (gc < NTOK)
                    Cb[(size_t)gr * ldc + gc] =
                        g * acc[mi][ni][0] + gather_x(img, tac, bt, gr, gc);
                if (gc + 1 < NTOK)
                    Cb[(size_t)gr * ldc + gc + 1] =
                        g * acc[mi][ni][1] + gather_x(img, tac, bt, gr, gc + 1);
                if (gc < NTOK)
                    Cb[(size_t)(gr + 8) * ldc + gc] =
                        g * acc[mi][ni][2] + gather_x(img, tac, bt, gr + 8, gc);
                if (gc + 1 < NTOK)
                    Cb[(size_t)(gr + 8) * ldc + gc + 1] =
                        g * acc[mi][ni][3] + gather_x(img, tac, bt, gr + 8, gc + 1);
            }
        }
    }
}

// ---------------------------------------------------------------------------
// 4) SPLIT=3 (3xTF32) GEMM: 3-stage cp.async, hi/lo split on consume,
//    chunk 32, one barrier per chunk, 2 CTAs/SM.
//    EPI 2: fused q/k projection (blockIdx.y selects B/bias/C), C = acc + bias[col]
//    EPI 3: C = acc (raw scores)
// ---------------------------------------------------------------------------
template <int EPI>
__global__ __launch_bounds__(256, 2)
void gemm_async3_kernel(const float* __restrict__ A, int lda, size_t strideA,
                        const float* __restrict__ B, int ldb, size_t strideB,
                        const float* __restrict__ B2,
                        int K,
                        const float* __restrict__ bias,
                        const float* __restrict__ bias2,
                        float* __restrict__ C, int ldc, size_t strideC,
                        float* __restrict__ C2) {
    extern __shared__ uint32_t sm[];
    const uint32_t smem_base = smem_u32(sm);

    const int bt = blockIdx.z;
    const int m0 = blockIdx.x * 128;
    int n0;
    const float* Bsel;
    const float* biassel;
    float* Csel;
    if (EPI == 2) {
        n0 = 0;
        const bool alt = (blockIdx.y != 0);
        Bsel = alt ? B2 : B;
        biassel = alt ? bias2 : bias;
        Csel = alt ? C2 : C;
    } else {
        n0 = blockIdx.y * 128;
        Bsel = B; biassel = bias; Csel = C;
    }

    const float* Ab = A + (size_t)bt * strideA + (size_t)m0 * lda;
    const float* Bb = Bsel + (size_t)bt * strideB + (size_t)n0 * ldb;

    const int t = threadIdx.x;
    const int wid = t >> 5, lane = t & 31;
    const int warp_m = wid & 1, warp_n = wid >> 1;
    const int l4 = lane >> 2, lm = lane & 3;

    const int prow = t >> 1;
    const int pcol = (t & 1) * 16;
    const float* aRow = Ab + (size_t)prow * lda + pcol;
    const float* bRow = Bb + (size_t)prow * ldb + pcol;
    const uint32_t sA0 = smem_base + (prow * LDS_S + pcol) * 4;
    const uint32_t sB0 = sA0 + TILEW * 4;

    float acc[4][4][4];
    #pragma unroll
    for (int mi = 0; mi < 4; mi++)
        #pragma unroll
        for (int ni = 0; ni < 4; ni++)
            #pragma unroll
            for (int r = 0; r < 4; r++) acc[mi][ni][r] = 0.0f;

    const int NCH = K / 32;

    #define ISSUE3(stg, koff) do {                                             \
        const uint32_t _dA = sA0 + (uint32_t)(stg) * (STAGEW * 4);             \
        const uint32_t _dB = sB0 + (uint32_t)(stg) * (STAGEW * 4);             \
        _Pragma("unroll")                                                      \
        for (int q = 0; q < 4; q++) {                                          \
            CP_ASYNC16(_dA + q * 16, aRow + (koff) + q * 4);                   \
            CP_ASYNC16(_dB + q * 16, bRow + (koff) + q * 4);                   \
        }                                                                      \
        CP_COMMIT();                                                           \
    } while (0)

    ISSUE3(0, 0);
    if (NCH > 1) ISSUE3(1, 32);

    for (int ch = 0; ch < NCH; ch++) {
        if (ch + 1 < NCH) CP_WAIT1(); else CP_WAIT0();
        __syncthreads();
        if (ch + 2 < NCH) ISSUE3((ch + 2) % 3, (ch + 2) * 32);

        const uint32_t* as = sm + (ch % 3) * STAGEW;
        const uint32_t* bs = as + TILEW;
        #pragma unroll
        for (int g = 0; g < 4; g++) {
            const int kk = g * 8;
            uint32_t bh[4][2], bl[4][2];
            #pragma unroll
            for (int ni = 0; ni < 4; ni++) {
                const int base = (warp_n * 32 + ni * 8 + l4) * LDS_S + kk + lm;
                const uint32_t r0 = bs[base], r1 = bs[base + 4];
                bh[ni][0] = u2tf(r0);
                bl[ni][0] = f2tf(__uint_as_float(r0) - __uint_as_float(bh[ni][0]));
                bh[ni][1] = u2tf(r1);
                bl[ni][1] = f2tf(__uint_as_float(r1) - __uint_as_float(bh[ni][1]));
            }
            #pragma unroll
            for (int mi = 0; mi < 4; mi++) {
                const int base = (warp_m * 64 + mi * 16 + l4) * LDS_S + kk + lm;
                uint32_t ar[4];
                ar[0] = as[base];
                ar[1] = as[base + 8 * LDS_S];
                ar[2] = as[base + 4];
                ar[3] = as[base + 8 * LDS_S + 4];
                uint32_t ah[4], al[4];
                #pragma unroll
                for (int r = 0; r < 4; r++) {
                    ah[r] = u2tf(ar[r]);
                    al[r] = f2tf(__uint_as_float(ar[r]) - __uint_as_float(ah[r]));
                }
                #pragma unroll
                for (int ni = 0; ni < 4; ni++) {
                    mma_tf32(acc[mi][ni], ah, bl[ni]);
                    mma_tf32(acc[mi][ni], al, bh[ni]);
                    mma_tf32(acc[mi][ni], ah, bh[ni]);
                }
            }
        }
    }
    #undef ISSUE3

    float* Cb = Csel + (size_t)bt * strideC;
    if (EPI == 2) {
        #pragma unroll
        for (int mi = 0; mi < 4; mi++) {
            const int gr = m0 + warp_m * 64 + mi * 16 + l4;
            #pragma unroll
            for (int ni = 0; ni < 4; ni++) {
                const int gc = n0 + warp_n * 32 + ni * 8 + lm * 2;
                const float b0 = biassel[gc], b1 = biassel[gc + 1];
                float2 o0 = { acc[mi][ni][0] + b0, acc[mi][ni][1] + b1 };
                float2 o1 = { acc[mi][ni][2] + b0, acc[mi][ni][3] + b1 };
                *reinterpret_cast<float2*>(&Cb[(size_t)gr * ldc + gc]) = o0;
                *reinterpret_cast<float2*>(&Cb[(size_t)(gr + 8) * ldc + gc]) = o1;
            }
        }
    } else {
        #pragma unroll
        for (int mi = 0; mi < 4; mi++) {
            const int gr = m0 + warp_m * 64 + mi * 16 + l4;
            #pragma unroll
            for (int ni = 0; ni < 4; ni++) {
                const int gc = n0 + warp_n * 32 + ni * 8 + lm * 2;
                float2 o0 = { acc[mi][ni][0], acc[mi][ni][1] };
                float2 o1 = { acc[mi][ni][2], acc[mi][ni][3] };
                *reinterpret_cast<float2*>(&Cb[(size_t)gr * ldc + gc]) = o0;
                *reinterpret_cast<float2*>(&Cb[(size_t)(gr + 8) * ldc + gc]) = o1;
            }
        }
    }
}

// ---------------------------------------------------------------------------
// Launch
// ---------------------------------------------------------------------------
extern "C" void kernel_launch(void* const* d_in, const int* in_sizes, int n_in,
                              void* d_out, int out_size) {
    const float* img   = (const float*)d_in[0];
    const float* tac   = (const float*)d_in[1];
    const float* Wq    = (const float*)d_in[2];
    const float* bq    = (const float*)d_in[3];
    const float* Wk    = (const float*)d_in[4];
    const float* bk    = (const float*)d_in[5];
    const float* Wv    = (const float*)d_in[6];
    const float* bv    = (const float*)d_in[7];
    const float* gamma = (const float*)d_in[8];
    float* out = (float*)d_out;

    float *gXT, *gXTh, *gWvh, *gQT, *gKT, *gV, *gA;
    cudaGetSymbolAddress((void**)&gXT,  g_XT);
    cudaGetSymbolAddress((void**)&gXTh, g_XTh);
    cudaGetSymbolAddress((void**)&gWvh, g_Wvh);
    cudaGetSymbolAddress((void**)&gQT,  g_QT);
    cudaGetSymbolAddress((void**)&gKT,  g_KT);
    cudaGetSymbolAddress((void**)&gV,   g_V);
    cudaGetSymbolAddress((void**)&gA,   g_ATT);

    cudaFuncSetAttribute(gemm_async_kernel<0>,  cudaFuncAttributeMaxDynamicSharedMemorySize, SMEM_T3);
    cudaFuncSetAttribute(gemm_async_kernel<1>,  cudaFuncAttributeMaxDynamicSharedMemorySize, SMEM_T3);
    cudaFuncSetAttribute(gemm_async3_kernel<2>, cudaFuncAttributeMaxDynamicSharedMemorySize, SMEM_T3);
    cudaFuncSetAttribute(gemm_async3_kernel<3>, cudaFuncAttributeMaxDynamicSharedMemorySize, SMEM_T3);

    // 1) XT (raw + rounded) + rounded Wv  (residual gathered in out epilogue)
    build_xt_kernel<<<dim3(CF / 256, NP, BT), 256>>>(img, tac);
    prep_round_kernel<<<(CF * CF + 255) / 256, 256>>>(Wv, gWvh, CF * CF);

    // 2) fused q+k projections (3xTF32, raw operands, split on consume)
    gemm_async3_kernel<2><<<dim3(NP / 128, 2, BT), 256, SMEM_T3>>>(
        gXT, CF, (size_t)NP * CF,
        Wq, CF, 0, Wk,
        CF, bq, bk,
        gQT, CQ, (size_t)NP * CQ, gKT);

    // 3) v projection (pre-rounded operands, no cvt in mainloop)
    gemm_async_kernel<0><<<dim3(CF / 128, NP / 128, BT), 256, SMEM_T3>>>(
        gWvh, CF, 0,
        gXTh, CF, (size_t)NP * CF,
        CF, bv, nullptr, nullptr, nullptr,
        gV, NP, (size_t)CF * NP);

    // 4) attention scores (3xTF32, raw q/k, split on consume)
    gemm_async3_kernel<3><<<dim3(NP / 128, NP / 128, BT), 256, SMEM_T3>>>(
        gQT, CQ, (size_t)NP * CQ,
        gKT, CQ, (size_t)NP * CQ, nullptr,
        CQ, nullptr, nullptr,
        gA, NP, (size_t)NP * NP, nullptr);

    // 5) softmax -> tf32-rounded probs
    softmax_kernel<<<dim3(NTOK, BT), 256>>>();

    // 6) out = gamma * (V @ P^T) + gather_x (fused residual)
    gemm_async_kernel<1><<<dim3(CF / 128, NP / 128, BT), 256, SMEM_T3>>>(
        gV, NP, (size_t)CF * NP,
        gA, NP, (size_t)NP * NP,
        NP, nullptr, gamma, img, tac,
        out, NTOK, (size_t)CF * NTOK);
}

// round 17
// speedup vs baseline: 1.1361x; 1.1361x over previous
#include <cuda_runtime.h>
#include <cuda_bf16.h>
#include <cstdint>

// ---------------------------------------------------------------------------
// Shapes
// ---------------------------------------------------------------------------
#define BT   12
#define CF   1024
#define CQ   128
#define NTOK 2401
#define NP   2432
#define HF   49

// ---------------------------------------------------------------------------
// Scratch
// ---------------------------------------------------------------------------
__device__ float    g_XTh[(size_t)BT * NP * CF];   // tf32-rounded XT (v path)
__device__ uint16_t g_X2h[(size_t)BT * NP * CF];   // bf16 hi of XT (q/k path)
__device__ uint16_t g_X2l[(size_t)BT * NP * CF];   // bf16 lo of XT
__device__ float    g_Wvh[(size_t)CF * CF];        // tf32-rounded Wv
__device__ uint16_t g_Wq2h[(size_t)CQ * CF];
__device__ uint16_t g_Wq2l[(size_t)CQ * CF];
__device__ uint16_t g_Wk2h[(size_t)CQ * CF];
__device__ uint16_t g_Wk2l[(size_t)CQ * CF];
__device__ uint16_t g_Q2h[(size_t)BT * NP * CQ];
__device__ uint16_t g_Q2l[(size_t)BT * NP * CQ];
__device__ uint16_t g_K2h[(size_t)BT * NP * CQ];
__device__ uint16_t g_K2l[(size_t)BT * NP * CQ];
__device__ float    g_V  [(size_t)BT * CF * NP];   // tf32-rounded v (incl bias)
__device__ float    g_ATT[(size_t)BT * NP * NP];   // raw scores -> rounded probs

__device__ __forceinline__ uint32_t f2tf(float f) {
    uint32_t u; asm("cvt.rna.tf32.f32 %0, %1;" : "=r"(u) : "f"(f)); return u;
}
__device__ __forceinline__ float tf32f(float f) { return __uint_as_float(f2tf(f)); }
__device__ __forceinline__ uint32_t smem_u32(const void* p) {
    uint32_t a;
    asm("{ .reg .u64 t; cvta.to.shared.u64 t, %1; cvt.u32.u64 %0, t; }" : "=r"(a) : "l"(p));
    return a;
}
__device__ __forceinline__ void split_bf16(float v, uint16_t& h, uint16_t& l) {
    __nv_bfloat16 hb = __float2bfloat16(v);
    h = __bfloat16_as_ushort(hb);
    l = __bfloat16_as_ushort(__float2bfloat16(v - __bfloat162float(hb)));
}

// residual gather: x[bt][c][n] straight from inputs (L2-resident)
__device__ __forceinline__ float gather_x(const float* __restrict__ img,
                                          const float* __restrict__ tac,
                                          int bt, int c, int n) {
    int i = n / HF, j = n % HF;
    return (c < 512)
        ? tac[(((size_t)bt * 512 + c) * 7 + (i / 7)) * 7 + (j / 7)]
        : img[(((size_t)bt * 512 + (c - 512)) * 7 + (i % 7)) * 7 + (j % 7)];
}

__device__ __forceinline__ void mma_tf32(float c[4], const uint32_t a[4], const uint32_t b[2]) {
    asm volatile(
        "mma.sync.aligned.m16n8k8.row.col.f32.tf32.tf32.f32 "
        "{%0,%1,%2,%3}, {%4,%5,%6,%7}, {%8,%9}, {%0,%1,%2,%3};"
        : "+f"(c[0]), "+f"(c[1]), "+f"(c[2]), "+f"(c[3])
        : "r"(a[0]), "r"(a[1]), "r"(a[2]), "r"(a[3]), "r"(b[0]), "r"(b[1]));
}
__device__ __forceinline__ void mma_bf16(float c[4], const uint32_t a[4], const uint32_t b[2]) {
    asm volatile(
        "mma.sync.aligned.m16n8k16.row.col.f32.bf16.bf16.f32 "
        "{%0,%1,%2,%3}, {%4,%5,%6,%7}, {%8,%9}, {%0,%1,%2,%3};"
        : "+f"(c[0]), "+f"(c[1]), "+f"(c[2]), "+f"(c[3])
        : "r"(a[0]), "r"(a[1]), "r"(a[2]), "r"(a[3]), "r"(b[0]), "r"(b[1]));
}

#define CP_ASYNC16(dst_u32, src_ptr) \
    asm volatile("cp.async.cg.shared.global [%0], [%1], 16;" :: "r"(dst_u32), "l"(src_ptr) : "memory")
#define CP_COMMIT() asm volatile("cp.async.commit_group;" ::: "memory")
#define CP_WAIT0()  asm volatile("cp.async.wait_group 0;" ::: "memory")

// ---------------------------------------------------------------------------
// 1) XT: tf32-rounded fp32 (v path) + bf16 hi/lo (q/k path)
// ---------------------------------------------------------------------------
__global__ void build_xt_kernel(const float* __restrict__ img,
                                const float* __restrict__ tac) {
    int c = blockIdx.x * 256 + threadIdx.x;
    int n = blockIdx.y, bt = blockIdx.z;
    if (c >= CF) return;
    float v = 0.0f;
    if (n < NTOK) v = gather_x(img, tac, bt, c, n);
    size_t base = ((size_t)bt * NP + n) * CF + c;
    g_XTh[base] = tf32f(v);
    uint16_t h, l;
    split_bf16(v, h, l);
    g_X2h[base] = h;
    g_X2l[base] = l;
}

// ---------------------------------------------------------------------------
// 1b) weight prep
// ---------------------------------------------------------------------------
__global__ void prep_round_kernel(const float* __restrict__ src,
                                  float* __restrict__ dst, int n) {
    int i = blockIdx.x * 256 + threadIdx.x;
    if (i < n) dst[i] = tf32f(src[i]);
}
__global__ void prep_split_bf16_kernel(const float* __restrict__ src,
                                       uint16_t* __restrict__ dh,
                                       uint16_t* __restrict__ dl, int n) {
    int i = blockIdx.x * 256 + threadIdx.x;
    if (i >= n) return;
    uint16_t h, l;
    split_bf16(src[i], h, l);
    dh[i] = h;
    dl[i] = l;
}

// ---------------------------------------------------------------------------
// 2) row softmax (m < 2401), writes tf32-rounded probs, zeroes padding
// ---------------------------------------------------------------------------
__global__ __launch_bounds__(256)
void softmax_kernel() {
    __shared__ float row[NTOK];
    __shared__ float red[256];
    const int n = blockIdx.x, bt = blockIdx.y;
    float* base = g_ATT + ((size_t)bt * NP + n) * NP;
    const int t = threadIdx.x;

    float mx = -1e30f;
    for (int m = t; m < NTOK; m += 256) { float v = base[m]; row[m] = v; mx = fmaxf(mx, v); }
    red[t] = mx; __syncthreads();
    for (int s = 128; s > 0; s >>= 1) { if (t < s) red[t] = fmaxf(red[t], red[t + s]); __syncthreads(); }
    mx = red[0]; __syncthreads();

    float sum = 0.0f;
    for (int m = t; m < NTOK; m += 256) { float e = __expf(row[m] - mx); row[m] = e; sum += e; }
    red[t] = sum; __syncthreads();
    for (int s = 128; s > 0; s >>= 1) { if (t < s) red[t] += red[t + s]; __syncthreads(); }
    float inv = 1.0f / red[0];

    for (int m = t; m < NTOK; m += 256) base[m] = tf32f(row[m] * inv);
    for (int m = NTOK + t; m < NP; m += 256) base[m] = 0.0f;
}

// ---------------------------------------------------------------------------
// Tiling constants
// ---------------------------------------------------------------------------
#define LDS_S 36
#define TILEW (128 * LDS_S)            // fp32 tile words (k32 rows)
#define SMEM_T (4 * TILEW * 4)         // 73728 B: tf32 double buffer

#define S2 20                          // bf16 kernel: words (bf16x2) per row stride
#define T2W (128 * S2)                 // words per 128-row tile (16 data words/row)
#define STG2W (4 * T2W)                // Ah, Al, Bh, Bl per stage
#define SMEM_B2 (2 * STG2W * 4)        // 81920 B double buffer

// ---------------------------------------------------------------------------
// 3) tf32 GEMM on PRE-ROUNDED operands (R15 form: one barrier per chunk).
//    EPI 0: C = tf32f(acc + bias[row])   EPI 1: C = gamma*acc + gather_x
// ---------------------------------------------------------------------------
template <int EPI>
__global__ __launch_bounds__(256, 2)
void gemm_async_kernel(const float* __restrict__ A, int lda, size_t strideA,
                       const float* __restrict__ B, int ldb, size_t strideB,
                       int K,
                       const float* __restrict__ bias,
                       const float* __restrict__ gamma,
                       const float* __restrict__ img,
                       const float* __restrict__ tac,
                       float* __restrict__ C, int ldc, size_t strideC) {
    extern __shared__ uint32_t sm[];
    const uint32_t smem_base = smem_u32(sm);

    const int bt = blockIdx.z;
    const int m0 = blockIdx.x * 128;
    const int n0 = blockIdx.y * 128;
    const float* Ab = A + (size_t)bt * strideA + (size_t)m0 * lda;
    const float* Bb = B + (size_t)bt * strideB + (size_t)n0 * ldb;

    const int t = threadIdx.x;
    const int wid = t >> 5, lane = t & 31;
    const int warp_m = wid & 1, warp_n = wid >> 1;
    const int l4 = lane >> 2, lm = lane & 3;

    const int prow = t >> 1;
    const int pcol = (t & 1) * 16;
    const float* aRow = Ab + (size_t)prow * lda + pcol;
    const float* bRow = Bb + (size_t)prow * ldb + pcol;
    const uint32_t sA0 = smem_base + (prow * LDS_S + pcol) * 4;
    const uint32_t sB0 = sA0 + TILEW * 4;

    float acc[4][4][4];
    #pragma unroll
    for (int mi = 0; mi < 4; mi++)
        #pragma unroll
        for (int ni = 0; ni < 4; ni++)
            #pragma unroll
            for (int r = 0; r < 4; r++) acc[mi][ni][r] = 0.0f;

    const int NCH = K / 32;

    #pragma unroll
    for (int q = 0; q < 4; q++) {
        CP_ASYNC16(sA0 + q * 16, aRow + q * 4);
        CP_ASYNC16(sB0 + q * 16, bRow + q * 4);
    }
    CP_COMMIT();

    for (int ch = 0; ch < NCH; ch++) {
        const int buf = ch & 1;
        CP_WAIT0();
        __syncthreads();
        if (ch + 1 < NCH) {
            const int k1 = (ch + 1) * 32;
            const uint32_t dA = sA0 + (buf ^ 1) * (2 * TILEW * 4);
            const uint32_t dB = sB0 + (buf ^ 1) * (2 * TILEW * 4);
            #pragma unroll
            for (int q = 0; q < 4; q++) {
                CP_ASYNC16(dA + q * 16, aRow + k1 + q * 4);
                CP_ASYNC16(dB + q * 16, bRow + k1 + q * 4);
            }
            CP_COMMIT();
        }

        const uint32_t* as = sm + buf * 2 * TILEW;
        const uint32_t* bs = as + TILEW;
        #pragma unroll
        for (int g = 0; g < 4; g++) {
            const int kk = g * 8;
            uint32_t b[4][2];
            #pragma unroll
            for (int ni = 0; ni < 4; ni++) {
                const int base = (warp_n * 32 + ni * 8 + l4) * LDS_S + kk + lm;
                b[ni][0] = bs[base];
                b[ni][1] = bs[base + 4];
            }
            #pragma unroll
            for (int mi = 0; mi < 4; mi++) {
                const int base = (warp_m * 64 + mi * 16 + l4) * LDS_S + kk + lm;
                uint32_t a[4];
                a[0] = as[base];
                a[1] = as[base + 8 * LDS_S];
                a[2] = as[base + 4];
                a[3] = as[base + 8 * LDS_S + 4];
                #pragma unroll
                for (int ni = 0; ni < 4; ni++) mma_tf32(acc[mi][ni], a, b[ni]);
            }
        }
    }

    float* Cb = C + (size_t)bt * strideC;
    if (EPI == 0) {
        #pragma unroll
        for (int mi = 0; mi < 4; mi++) {
            const int gr = m0 + warp_m * 64 + mi * 16 + l4;
            const float bv0 = bias[gr], bv8 = bias[gr + 8];
            #pragma unroll
            for (int ni = 0; ni < 4; ni++) {
                const int gc = n0 + warp_n * 32 + ni * 8 + lm * 2;
                float2 o0 = { tf32f(acc[mi][ni][0] + bv0), tf32f(acc[mi][ni][1] + bv0) };
                float2 o1 = { tf32f(acc[mi][ni][2] + bv8), tf32f(acc[mi][ni][3] + bv8) };
                *reinterpret_cast<float2*>(&Cb[(size_t)gr * ldc + gc]) = o0;
                *reinterpret_cast<float2*>(&Cb[(size_t)(gr + 8) * ldc + gc]) = o1;
            }
        }
    } else {
        const float g = __ldg(gamma);
        #pragma unroll
        for (int mi = 0; mi < 4; mi++) {
            const int gr = m0 + warp_m * 64 + mi * 16 + l4;
            #pragma unroll
            for (int ni = 0; ni < 4; ni++) {
                const int gc = n0 + warp_n * 32 + ni * 8 + lm * 2;
                if (gc < NTOK)
                    Cb[(size_t)gr * ldc + gc] =
                        g * acc[mi][ni][0] + gather_x(img, tac, bt, gr, gc);
                if (gc + 1 < NTOK)
                    Cb[(size_t)gr * ldc + gc + 1] =
                        g * acc[mi][ni][1] + gather_x(img, tac, bt, gr, gc + 1);
                if (gc < NTOK)
                    Cb[(size_t)(gr + 8) * ldc + gc] =
                        g * acc[mi][ni][2] + gather_x(img, tac, bt, gr + 8, gc);
                if (gc + 1 < NTOK)
                    Cb[(size_t)(gr + 8) * ldc + gc + 1] =
                        g * acc[mi][ni][3] + gather_x(img, tac, bt, gr + 8, gc + 1);
            }
        }
    }
}

// ---------------------------------------------------------------------------
// 4) bf16-split2 GEMM (m16n8k16): operands pre-split hi/lo packed bf16.
//    Per k16: 3 MMAs (hh, hl, lh). Chunk 32, one barrier/chunk, 2 CTAs/SM.
//    EPI 2: fused q/k projection (blockIdx.y selects); writes pre-split bf16
//    EPI 3: raw fp32 scores
// ---------------------------------------------------------------------------
template <int EPI>
__global__ __launch_bounds__(256, 2)
void gemm_bf16_kernel(const uint16_t* __restrict__ Ah, const uint16_t* __restrict__ Al,
                      int lda, size_t strideA,
                      const uint16_t* __restrict__ Bh, const uint16_t* __restrict__ Bl,
                      const uint16_t* __restrict__ B2h, const uint16_t* __restrict__ B2l,
                      int ldb, size_t strideB,
                      int K,
                      const float* __restrict__ bias, const float* __restrict__ bias2,
                      uint16_t* __restrict__ Ch, uint16_t* __restrict__ Cl,
                      uint16_t* __restrict__ C2h, uint16_t* __restrict__ C2l,
                      float* __restrict__ Cf,
                      int ldc, size_t strideC) {
    extern __shared__ uint32_t sm[];
    const uint32_t smem_base = smem_u32(sm);

    const int bt = blockIdx.z;
    const int m0 = blockIdx.x * 128;
    int n0;
    const uint16_t *Bhs, *Bls;
    const float* biassel;
    uint16_t *Chs, *Cls;
    if (EPI == 2) {
        n0 = 0;
        const bool alt = (blockIdx.y != 0);
        Bhs = alt ? B2h : Bh;  Bls = alt ? B2l : Bl;
        biassel = alt ? bias2 : bias;
        Chs = alt ? C2h : Ch;  Cls = alt ? C2l : Cl;
    } else {
        n0 = blockIdx.y * 128;
        Bhs = Bh; Bls = Bl; biassel = bias; Chs = Ch; Cls = Cl;
    }

    const uint16_t* Ahb = Ah  + (size_t)bt * strideA + (size_t)m0 * lda;
    const uint16_t* Alb = Al  + (size_t)bt * strideA + (size_t)m0 * lda;
    const uint16_t* Bhb = Bhs + (size_t)bt * strideB + (size_t)n0 * ldb;
    const uint16_t* Blb = Bls + (size_t)bt * strideB + (size_t)n0 * ldb;

    const int t = threadIdx.x;
    const int wid = t >> 5, lane = t & 31;
    const int wm = wid & 1, wn = wid >> 1;
    const int l4 = lane >> 2, lm = lane & 3;

    // producer: tile = t>>6 (0:Ah 1:Al 2:Bh 3:Bl), 2 rows/thread, 4 x 16B per row pair? 
    // each row of chunk = 32 bf16 = 64B = 4 granules; thread covers rows 2p, 2p+1 (2 granules each)
    const int ptile = t >> 6, plocal = t & 63;
    const uint16_t* tsrc = (ptile == 0) ? Ahb : (ptile == 1) ? Alb : (ptile == 2) ? Bhb : Blb;
    const int pld = (ptile < 2) ? lda : ldb;
    const int pr0 = plocal * 2;
    const uint32_t pDst0 = smem_base + (uint32_t)((ptile * T2W + pr0 * S2) * 4);

    float acc[4][4][4];
    #pragma unroll
    for (int mi = 0; mi < 4; mi++)
        #pragma unroll
        for (int ni = 0; ni < 4; ni++)
            #pragma unroll
            for (int r = 0; r < 4; r++) acc[mi][ni][r] = 0.0f;

    const int NCH = K / 32;

    #define B2_ISSUE(stg, koff) do {                                           \
        const uint32_t _d = pDst0 + (uint32_t)(stg) * (STG2W * 4);             \
        _Pragma("unroll")                                                      \
        for (int i = 0; i < 8; i++) {                                          \
            const int rr = i >> 2, q = i & 3;                                  \
            CP_ASYNC16(_d + rr * (S2 * 4) + q * 16,                            \
                       tsrc + (size_t)(pr0 + rr) * pld + (koff) + q * 8);      \
        }                                                                      \
        CP_COMMIT();                                                           \
    } while (0)

    B2_ISSUE(0, 0);

    for (int ch = 0; ch < NCH; ch++) {
        const int buf = ch & 1;
        CP_WAIT0();
        __syncthreads();
        if (ch + 1 < NCH) B2_ISSUE(buf ^ 1, (ch + 1) * 32);

        const uint32_t* ahs = sm + buf * STG2W;
        const uint32_t* als = ahs + T2W;
        const uint32_t* bhs = ahs + 2 * T2W;
        const uint32_t* bls = ahs + 3 * T2W;
        #pragma unroll
        for (int g = 0; g < 2; g++) {
            const int kk = g * 8;
            uint32_t bh[4][2], bl[4][2];
            #pragma unroll
            for (int ni = 0; ni < 4; ni++) {
                const int ro = (wn * 32 + ni * 8 + l4) * S2 + kk + lm;
                bh[ni][0] = bhs[ro];  bh[ni][1] = bhs[ro + 4];
                bl[ni][0] = bls[ro];  bl[ni][1] = bls[ro + 4];
            }
            #pragma unroll
            for (int mi = 0; mi < 4; mi++) {
                const int ro = (wm * 64 + mi * 16 + l4) * S2 + kk + lm;
                uint32_t ah_[4], al_[4];
                ah_[0] = ahs[ro];              al_[0] = als[ro];
                ah_[1] = ahs[ro + 8 * S2];     al_[1] = als[ro + 8 * S2];
                ah_[2] = ahs[ro + 4];          al_[2] = als[ro + 4];
                ah_[3] = ahs[ro + 8 * S2 + 4]; al_[3] = als[ro + 8 * S2 + 4];
                #pragma unroll
                for (int ni = 0; ni < 4; ni++) {
                    mma_bf16(acc[mi][ni], ah_, bl[ni]);
                    mma_bf16(acc[mi][ni], al_, bh[ni]);
                    mma_bf16(acc[mi][ni], ah_, bh[ni]);
                }
            }
        }
    }
    #undef B2_ISSUE

    if (EPI == 2) {
        uint16_t* Cbh = Chs + (size_t)bt * strideC;
        uint16_t* Cbl = Cls + (size_t)bt * strideC;
        #pragma unroll
        for (int mi = 0; mi < 4; mi++) {
            const int gr = m0 + wm * 64 + mi * 16 + l4;
            #pragma unroll
            for (int ni = 0; ni < 4; ni++) {
                const int gc = n0 + wn * 32 + ni * 8 + lm * 2;
                const float b0 = biassel[gc], b1 = biassel[gc + 1];
                float vv[4] = { acc[mi][ni][0] + b0, acc[mi][ni][1] + b1,
                                acc[mi][ni][2] + b0, acc[mi][ni][3] + b1 };
                uint16_t h[4], l[4];
                #pragma unroll
                for (int r = 0; r < 4; r++) split_bf16(vv[r], h[r], l[r]);
                const size_t o0 = (size_t)gr * ldc + gc;
                const size_t o1 = (size_t)(gr + 8) * ldc + gc;
                *reinterpret_cast<uint32_t*>(&Cbh[o0]) = (uint32_t)h[0] | ((uint32_t)h[1] << 16);
                *reinterpret_cast<uint32_t*>(&Cbl[o0]) = (uint32_t)l[0] | ((uint32_t)l[1] << 16);
                *reinterpret_cast<uint32_t*>(&Cbh[o1]) = (uint32_t)h[2] | ((uint32_t)h[3] << 16);
                *reinterpret_cast<uint32_t*>(&Cbl[o1]) = (uint32_t)l[2] | ((uint32_t)l[3] << 16);
            }
        }
    } else {
        float* Cb = Cf + (size_t)bt * strideC;
        #pragma unroll
        for (int mi = 0; mi < 4; mi++) {
            const int gr = m0 + wm * 64 + mi * 16 + l4;
            #pragma unroll
            for (int ni = 0; ni < 4; ni++) {
                const int gc = n0 + wn * 32 + ni * 8 + lm * 2;
                float2 o0 = { acc[mi][ni][0], acc[mi][ni][1] };
                float2 o1 = { acc[mi][ni][2], acc[mi][ni][3] };
                *reinterpret_cast<float2*>(&Cb[(size_t)gr * ldc + gc]) = o0;
                *reinterpret_cast<float2*>(&Cb[(size_t)(gr + 8) * ldc + gc]) = o1;
            }
        }
    }
}

// ---------------------------------------------------------------------------
// Launch
// ---------------------------------------------------------------------------
extern "C" void kernel_launch(void* const* d_in, const int* in_sizes, int n_in,
                              void* d_out, int out_size) {
    const float* img   = (const float*)d_in[0];
    const float* tac   = (const float*)d_in[1];
    const float* Wq    = (const float*)d_in[2];
    const float* bq    = (const float*)d_in[3];
    const float* Wk    = (const float*)d_in[4];
    const float* bk    = (const float*)d_in[5];
    const float* Wv    = (const float*)d_in[6];
    const float* bv    = (const float*)d_in[7];
    const float* gamma = (const float*)d_in[8];
    float* out = (float*)d_out;

    float *gXTh, *gWvh, *gV, *gA;
    uint16_t *gX2h, *gX2l, *gWq2h, *gWq2l, *gWk2h, *gWk2l;
    uint16_t *gQ2h, *gQ2l, *gK2h, *gK2l;
    cudaGetSymbolAddress((void**)&gXTh, g_XTh);
    cudaGetSymbolAddress((void**)&gX2h, g_X2h);
    cudaGetSymbolAddress((void**)&gX2l, g_X2l);
    cudaGetSymbolAddress((void**)&gWvh, g_Wvh);
    cudaGetSymbolAddress((void**)&gWq2h, g_Wq2h);
    cudaGetSymbolAddress((void**)&gWq2l, g_Wq2l);
    cudaGetSymbolAddress((void**)&gWk2h, g_Wk2h);
    cudaGetSymbolAddress((void**)&gWk2l, g_Wk2l);
    cudaGetSymbolAddress((void**)&gQ2h, g_Q2h);
    cudaGetSymbolAddress((void**)&gQ2l, g_Q2l);
    cudaGetSymbolAddress((void**)&gK2h, g_K2h);
    cudaGetSymbolAddress((void**)&gK2l, g_K2l);
    cudaGetSymbolAddress((void**)&gV,   g_V);
    cudaGetSymbolAddress((void**)&gA,   g_ATT);

    cudaFuncSetAttribute(gemm_async_kernel<0>, cudaFuncAttributeMaxDynamicSharedMemorySize, SMEM_T);
    cudaFuncSetAttribute(gemm_async_kernel<1>, cudaFuncAttributeMaxDynamicSharedMemorySize, SMEM_T);
    cudaFuncSetAttribute(gemm_bf16_kernel<2>,  cudaFuncAttributeMaxDynamicSharedMemorySize, SMEM_B2);
    cudaFuncSetAttribute(gemm_bf16_kernel<3>,  cudaFuncAttributeMaxDynamicSharedMemorySize, SMEM_B2);

    // 1) XT (tf32 + bf16-split) + weight prep
    build_xt_kernel<<<dim3(CF / 256, NP, BT), 256>>>(img, tac);
    prep_round_kernel<<<(CF * CF + 255) / 256, 256>>>(Wv, gWvh, CF * CF);
    prep_split_bf16_kernel<<<(CQ * CF + 255) / 256, 256>>>(Wq, gWq2h, gWq2l, CQ * CF);
    prep_split_bf16_kernel<<<(CQ * CF + 255) / 256, 256>>>(Wk, gWk2h, gWk2l, CQ * CF);

    // 2) fused q+k projections (bf16-split2): QT/KT[n][o] pre-split bf16
    gemm_bf16_kernel<2><<<dim3(NP / 128, 2, BT), 256, SMEM_B2>>>(
        gX2h, gX2l, CF, (size_t)NP * CF,
        gWq2h, gWq2l, gWk2h, gWk2l, CF, 0,
        CF, bq, bk,
        gQ2h, gQ2l, gK2h, gK2l, nullptr,
        CQ, (size_t)NP * CQ);

    // 3) v projection (tf32, pre-rounded)
    gemm_async_kernel<0><<<dim3(CF / 128, NP / 128, BT), 256, SMEM_T>>>(
        gWvh, CF, 0,
        gXTh, CF, (size_t)NP * CF,
        CF, bv, nullptr, nullptr, nullptr,
        gV, NP, (size_t)CF * NP);

    // 4) attention scores (bf16-split2): raw S[n][m]
    gemm_bf16_kernel<3><<<dim3(NP / 128, NP / 128, BT), 256, SMEM_B2>>>(
        gQ2h, gQ2l, CQ, (size_t)NP * CQ,
        gK2h, gK2l, nullptr, nullptr, CQ, (size_t)NP * CQ,
        CQ, nullptr, nullptr,
        nullptr, nullptr, nullptr, nullptr, gA,
        NP, (size_t)NP * NP);

    // 5) softmax -> tf32-rounded probs
    softmax_kernel<<<dim3(NTOK, BT), 256>>>();

    // 6) out = gamma * (V @ P^T) + gather_x (tf32)
    gemm_async_kernel<1><<<dim3(CF / 128, NP / 128, BT), 256, SMEM_T>>>(
        gV, NP, (size_t)CF * NP,
        gA, NP, (size_t)NP * NP,
        NP, nullptr, gamma, img, tac,
        out, NTOK, (size_t)CF * NTOK);
}